// round 3
// baseline (speedup 1.0000x reference)
#include <cuda_runtime.h>
#include <cstdint>

#define MAX_NODES 100000
#define MAX_EDGES 1700000
#define F1 32
#define F2 16
#define F3 2

#define SCAN_B 1024
#define N_SCAN_BLOCKS ((MAX_NODES + SCAN_B - 1) / SCAN_B)   // 98

// Scratch (device globals; no allocation allowed)
__device__ __align__(256) float g_y1[MAX_NODES * F1];
__device__ __align__(256) float g_h1[MAX_NODES * F1];
__device__ __align__(256) float g_y2[MAX_NODES * F2];
__device__ __align__(256) float g_h2[MAX_NODES * F2];
__device__ __align__(256) float g_y3[MAX_NODES * F3];
__device__ __align__(256) float g_h3[MAX_NODES * F3];

__device__ __align__(256) int g_cnt[MAX_NODES];        // histogram
__device__ __align__(256) int g_cur[MAX_NODES];        // fill cursor
__device__ __align__(256) int g_row[MAX_NODES + 1];    // CSR row offsets
__device__ __align__(256) int g_bsum[N_SCAN_BLOCKS];   // scan spine
__device__ __align__(256) int g_srcs[MAX_EDGES];       // CSR column (src ids)

// ---------------------------------------------------------------------------
// CSR build
// ---------------------------------------------------------------------------
__global__ void zero_k(int* __restrict__ c, int n) {
    int i = blockIdx.x * blockDim.x + threadIdx.x;
    if (i < n) c[i] = 0;
}

__global__ void hist_k(const int* __restrict__ ei, int* __restrict__ cnt, int e) {
    int t = blockIdx.x * blockDim.x + threadIdx.x;
    if (t < e) atomicAdd(&cnt[ei[e + t]], 1);
}

// Per-block partial sums of the histogram.
__global__ void scan_partial_k(const int* __restrict__ cnt, int* __restrict__ bsum, int n) {
    __shared__ int s[SCAN_B];
    int i = blockIdx.x * SCAN_B + threadIdx.x;
    s[threadIdx.x] = (i < n) ? cnt[i] : 0;
    __syncthreads();
    for (int off = SCAN_B / 2; off > 0; off >>= 1) {
        if (threadIdx.x < off) s[threadIdx.x] += s[threadIdx.x + off];
        __syncthreads();
    }
    if (threadIdx.x == 0) bsum[blockIdx.x] = s[0];
}

// Exclusive scan of the <=128 block sums; also writes row[N] = e.
__global__ void scan_spine_k(int* __restrict__ bsum, int* __restrict__ row, int nb, int n, int e) {
    __shared__ int s[128];
    int t = threadIdx.x;
    int v = (t < nb) ? bsum[t] : 0;
    s[t] = v;
    __syncthreads();
    for (int off = 1; off < 128; off <<= 1) {
        int x = (t >= off) ? s[t - off] : 0;
        __syncthreads();
        s[t] += x;
        __syncthreads();
    }
    if (t < nb) bsum[t] = s[t] - v;  // exclusive
    if (t == 0) row[n] = e;
}

// Final scan: row[i] = bsum[b] + exclusive-within-block; also seed cursor.
__global__ void scan_final_k(const int* __restrict__ cnt, const int* __restrict__ bsum,
                             int* __restrict__ row, int* __restrict__ cur, int n) {
    __shared__ int s[SCAN_B];
    int i = blockIdx.x * SCAN_B + threadIdx.x;
    int v = (i < n) ? cnt[i] : 0;
    s[threadIdx.x] = v;
    __syncthreads();
    for (int off = 1; off < SCAN_B; off <<= 1) {
        int x = (threadIdx.x >= off) ? s[threadIdx.x - off] : 0;
        __syncthreads();
        s[threadIdx.x] += x;
        __syncthreads();
    }
    if (i < n) {
        int excl = bsum[blockIdx.x] + s[threadIdx.x] - v;
        row[i] = excl;
        cur[i] = excl;
    }
}

__global__ void fill_k(const int* __restrict__ ei, int* __restrict__ cur,
                       int* __restrict__ srcs, int e) {
    int t = blockIdx.x * blockDim.x + threadIdx.x;
    if (t < e) {
        int dst = ei[e + t];
        int pos = atomicAdd(&cur[dst], 1);
        srcs[pos] = ei[t];
    }
}

// ---------------------------------------------------------------------------
// Dense transform: y = act(x) @ Wrel ; h = act(x) @ Wroot + b
// ---------------------------------------------------------------------------
template <int FIN, int FOUT, bool RELU>
__global__ void transform_k(const float* __restrict__ x,
                            const float* __restrict__ Wrel,
                            const float* __restrict__ Wroot,
                            const float* __restrict__ b,
                            float* __restrict__ y,
                            float* __restrict__ h,
                            int n) {
    __shared__ float s_rel[FIN * FOUT];
    __shared__ float s_root[FIN * FOUT];
    __shared__ float s_b[FOUT];
    for (int i = threadIdx.x; i < FIN * FOUT; i += blockDim.x) {
        s_rel[i]  = Wrel[i];
        s_root[i] = Wroot[i];
    }
    for (int i = threadIdx.x; i < FOUT; i += blockDim.x) s_b[i] = b[i];
    __syncthreads();

    int node = blockIdx.x * blockDim.x + threadIdx.x;
    if (node >= n) return;

    float accR[FOUT];
    float accO[FOUT];
#pragma unroll
    for (int j = 0; j < FOUT; j++) { accR[j] = 0.f; accO[j] = 0.f; }

    const float4* xr = reinterpret_cast<const float4*>(x + (size_t)node * FIN);
#pragma unroll
    for (int kk = 0; kk < FIN / 4; kk++) {
        float4 xv = __ldg(xr + kk);
        float xs[4] = {xv.x, xv.y, xv.z, xv.w};
#pragma unroll
        for (int q = 0; q < 4; q++) {
            float v = RELU ? fmaxf(xs[q], 0.f) : xs[q];
            const int k = kk * 4 + q;
#pragma unroll
            for (int j = 0; j < FOUT; j++) {
                accR[j] = fmaf(v, s_rel[k * FOUT + j], accR[j]);
                accO[j] = fmaf(v, s_root[k * FOUT + j], accO[j]);
            }
        }
    }

    float* yo = y + (size_t)node * FOUT;
    float* ho = h + (size_t)node * FOUT;
#pragma unroll
    for (int j = 0; j < FOUT; j++) {
        yo[j] = accR[j];
        ho[j] = accO[j] + s_b[j];
    }
}

// ---------------------------------------------------------------------------
// CSR aggregation: one warp per node. Lanes split into CH=F/4 chunks per row,
// RPI=32/CH edges in flight. h[node] += sum_{src in N(node)} y[src]  (in place:
// h already holds the root+bias term).
// ---------------------------------------------------------------------------
template <int F>
__global__ void agg_k(const int* __restrict__ row, const int* __restrict__ srcs,
                      const float* __restrict__ y, float* __restrict__ h, int n) {
    constexpr int CH  = F / 4;     // float4 chunks per row
    constexpr int RPI = 32 / CH;   // rows (edges) per warp-iteration
    int w = (blockIdx.x * blockDim.x + threadIdx.x) >> 5;
    if (w >= n) return;
    int lane = threadIdx.x & 31;
    int sub  = lane / CH;
    int c    = lane % CH;
    int start = row[w], end = row[w + 1];

    float4 acc = make_float4(0.f, 0.f, 0.f, 0.f);
    for (int i = start + sub; i < end; i += RPI) {
        int src = srcs[i];
        float4 v = __ldg(reinterpret_cast<const float4*>(y + (size_t)src * F + c * 4));
        acc.x += v.x; acc.y += v.y; acc.z += v.z; acc.w += v.w;
    }
#pragma unroll
    for (int off = 16; off >= CH; off >>= 1) {
        acc.x += __shfl_down_sync(0xffffffff, acc.x, off);
        acc.y += __shfl_down_sync(0xffffffff, acc.y, off);
        acc.z += __shfl_down_sync(0xffffffff, acc.z, off);
        acc.w += __shfl_down_sync(0xffffffff, acc.w, off);
    }
    if (lane < CH) {
        float4* hp = reinterpret_cast<float4*>(h + (size_t)w * F + lane * 4);
        float4 r = *hp;
        r.x += acc.x; r.y += acc.y; r.z += acc.z; r.w += acc.w;
        *hp = r;
    }
}

// Layer-3 aggregation (F=2) fused with softmax: one warp per node, one lane per edge.
__global__ void agg2_softmax_k(const int* __restrict__ row, const int* __restrict__ srcs,
                               const float* __restrict__ y, const float* __restrict__ h,
                               float* __restrict__ out, int n) {
    int w = (blockIdx.x * blockDim.x + threadIdx.x) >> 5;
    if (w >= n) return;
    int lane = threadIdx.x & 31;
    int start = row[w], end = row[w + 1];

    float ax = 0.f, ay = 0.f;
    for (int i = start + lane; i < end; i += 32) {
        int src = srcs[i];
        float2 v = __ldg(reinterpret_cast<const float2*>(y + 2 * (size_t)src));
        ax += v.x; ay += v.y;
    }
#pragma unroll
    for (int off = 16; off > 0; off >>= 1) {
        ax += __shfl_down_sync(0xffffffff, ax, off);
        ay += __shfl_down_sync(0xffffffff, ay, off);
    }
    if (lane == 0) {
        float2 r = *reinterpret_cast<const float2*>(h + 2 * (size_t)w);
        float vx = r.x + ax, vy = r.y + ay;
        float m  = fmaxf(vx, vy);
        float ea = __expf(vx - m);
        float eb = __expf(vy - m);
        float inv = 1.0f / (ea + eb);
        reinterpret_cast<float2*>(out)[w] = make_float2(ea * inv, eb * inv);
    }
}

extern "C" void kernel_launch(void* const* d_in, const int* in_sizes, int n_in,
                              void* d_out, int out_size) {
    const float* z      = (const float*)d_in[0];
    const int*   ei     = (const int*)d_in[1];   // int32 (JAX x64 disabled)
    const float* Wrel1  = (const float*)d_in[2];
    const float* Wroot1 = (const float*)d_in[3];
    const float* b1     = (const float*)d_in[4];
    const float* Wrel2  = (const float*)d_in[5];
    const float* Wroot2 = (const float*)d_in[6];
    const float* b2     = (const float*)d_in[7];
    const float* Wrel3  = (const float*)d_in[8];
    const float* Wroot3 = (const float*)d_in[9];
    const float* b3     = (const float*)d_in[10];

    const int n = in_sizes[0] / 64;   // 100000
    const int e = in_sizes[1] / 2;    // 1600000

    float *y1, *h1, *y2, *h2, *y3, *h3;
    int *cnt, *cur, *rowp, *bsum, *srcs;
    cudaGetSymbolAddress((void**)&y1, g_y1);
    cudaGetSymbolAddress((void**)&h1, g_h1);
    cudaGetSymbolAddress((void**)&y2, g_y2);
    cudaGetSymbolAddress((void**)&h2, g_h2);
    cudaGetSymbolAddress((void**)&y3, g_y3);
    cudaGetSymbolAddress((void**)&h3, g_h3);
    cudaGetSymbolAddress((void**)&cnt,  g_cnt);
    cudaGetSymbolAddress((void**)&cur,  g_cur);
    cudaGetSymbolAddress((void**)&rowp, g_row);
    cudaGetSymbolAddress((void**)&bsum, g_bsum);
    cudaGetSymbolAddress((void**)&srcs, g_srcs);

    const int nScanBlocks = (n + SCAN_B - 1) / SCAN_B;  // 98
    const int TB = 128;
    const int nodeBlocks = (n + TB - 1) / TB;
    const int edgeBlocks = (e + 255) / 256;
    const int warpBlocks = (n + 7) / 8;  // 8 warps (256 threads) per block

    // ---- CSR build (reused by all 3 layers) ----
    zero_k<<<(n + 255) / 256, 256>>>(cnt, n);
    hist_k<<<edgeBlocks, 256>>>(ei, cnt, e);
    scan_partial_k<<<nScanBlocks, SCAN_B>>>(cnt, bsum, n);
    scan_spine_k<<<1, 128>>>(bsum, rowp, nScanBlocks, n, e);
    scan_final_k<<<nScanBlocks, SCAN_B>>>(cnt, bsum, rowp, cur, n);
    fill_k<<<edgeBlocks, 256>>>(ei, cur, srcs, e);

    // ---- Layer 1 ----
    transform_k<64, F1, false><<<nodeBlocks, TB>>>(z, Wrel1, Wroot1, b1, y1, h1, n);
    agg_k<F1><<<warpBlocks, 256>>>(rowp, srcs, y1, h1, n);
    // ---- Layer 2 (ReLU applied on read of h1) ----
    transform_k<F1, F2, true><<<nodeBlocks, TB>>>(h1, Wrel2, Wroot2, b2, y2, h2, n);
    agg_k<F2><<<warpBlocks, 256>>>(rowp, srcs, y2, h2, n);
    // ---- Layer 3 + fused softmax ----
    transform_k<F2, F3, true><<<nodeBlocks, TB>>>(h2, Wrel3, Wroot3, b3, y3, h3, n);
    agg2_softmax_k<<<warpBlocks, 256>>>(rowp, srcs, y3, h3, (float*)d_out, n);
}

// round 4
// speedup vs baseline: 1.0623x; 1.0623x over previous
#include <cuda_runtime.h>
#include <cstdint>

#define MAX_NODES 100000
#define F1 32
#define F2 16
#define F3 2

// Scratch (device globals; no allocation allowed)
__device__ __align__(256) float g_y1[MAX_NODES * F1];
__device__ __align__(256) float g_h1[MAX_NODES * F1];
__device__ __align__(256) float g_y2[MAX_NODES * F2];
__device__ __align__(256) float g_h2[MAX_NODES * F2];
__device__ __align__(256) float g_y3[MAX_NODES * F3];
__device__ __align__(256) float g_h3[MAX_NODES * F3];

// Grid barrier state (count resets to 0 at every barrier; gen monotonic)
__device__ unsigned g_bar_cnt = 0;
__device__ volatile unsigned g_bar_gen = 0;

__device__ __forceinline__ void grid_sync() {
    __syncthreads();
    if (threadIdx.x == 0) {
        __threadfence();                       // release all prior writes
        unsigned gen = g_bar_gen;
        unsigned arrived = atomicAdd(&g_bar_cnt, 1u);
        if (arrived == gridDim.x - 1) {
            g_bar_cnt = 0;
            __threadfence();
            g_bar_gen = gen + 1;               // publish
        } else {
            while (g_bar_gen == gen) { }       // spin
            __threadfence();                   // acquire
        }
    }
    __syncthreads();
}

// ---------------------------------------------------------------------------
// Transform phase: items 0..n-1 compute y[node] = act(x) @ Wrel (rel threads),
// items n..2n-1 compute h[node] = act(x) @ Wroot + b (root threads).
// Splitting rel/root halves accumulator register pressure vs. computing both.
// Weights staged in SMEM; lanes broadcast-read the same weight per FMA.
// ---------------------------------------------------------------------------
template <int FIN, int FOUT, bool RELU>
__device__ __forceinline__ void transform_phase(
    const float* __restrict__ x,
    const float* __restrict__ Wrel, const float* __restrict__ Wroot,
    const float* __restrict__ b,
    float* __restrict__ y, float* __restrict__ h,
    int n, float* s_w, int gtid, int T) {

    // Stage: [0, FIN*FOUT) = Wrel, [FIN*FOUT, 2*FIN*FOUT) = Wroot, then bias
    for (int i = threadIdx.x; i < FIN * FOUT; i += blockDim.x) {
        s_w[i] = Wrel[i];
        s_w[FIN * FOUT + i] = Wroot[i];
    }
    for (int i = threadIdx.x; i < FOUT; i += blockDim.x)
        s_w[2 * FIN * FOUT + i] = b[i];
    __syncthreads();

    const float* s_b = s_w + 2 * FIN * FOUT;

    for (int it = gtid; it < 2 * n; it += T) {
        const bool isRel = it < n;
        const int node = isRel ? it : it - n;
        const float* W = isRel ? s_w : (s_w + FIN * FOUT);

        float acc[FOUT];
#pragma unroll
        for (int j = 0; j < FOUT; j++) acc[j] = isRel ? 0.f : s_b[j];

        const float4* xr = reinterpret_cast<const float4*>(x + (size_t)node * FIN);
#pragma unroll 4
        for (int kk = 0; kk < FIN / 4; kk++) {
            float4 xv = __ldg(xr + kk);
            float xs[4] = {xv.x, xv.y, xv.z, xv.w};
#pragma unroll
            for (int q = 0; q < 4; q++) {
                float v = RELU ? fmaxf(xs[q], 0.f) : xs[q];
                const int k = kk * 4 + q;
#pragma unroll
                for (int j = 0; j < FOUT; j++)
                    acc[j] = fmaf(v, W[k * FOUT + j], acc[j]);
            }
        }

        float* o = (isRel ? y : h) + (size_t)node * FOUT;
        if (FOUT >= 4) {
#pragma unroll
            for (int j = 0; j < FOUT / 4; j++)
                reinterpret_cast<float4*>(o)[j] =
                    make_float4(acc[j * 4], acc[j * 4 + 1], acc[j * 4 + 2], acc[j * 4 + 3]);
        } else {
#pragma unroll
            for (int j = 0; j < FOUT; j++) o[j] = acc[j];
        }
    }
}

// ---------------------------------------------------------------------------
// Scatter phase: h[dst] += y[src] via red.global.add.v4.f32, F/4 chunk-threads
// per edge (consecutive lanes cover one contiguous row).
// ---------------------------------------------------------------------------
template <int F>
__device__ __forceinline__ void scatter_phase(
    const int* __restrict__ ei, const float* __restrict__ y,
    float* __restrict__ h, int e, int gtid, int T) {
    constexpr int CH = F / 4;
    const int total = e * CH;
#pragma unroll 4
    for (int t = gtid; t < total; t += T) {
        int edge = t / CH;
        int c    = t % CH;
        int src = __ldg(ei + edge);
        int dst = __ldg(ei + e + edge);
        float4 v = __ldg(reinterpret_cast<const float4*>(y + (size_t)src * F + c * 4));
        float* p = h + (size_t)dst * F + c * 4;
        asm volatile("red.global.add.v4.f32 [%0], {%1, %2, %3, %4};"
                     :: "l"(p), "f"(v.x), "f"(v.y), "f"(v.z), "f"(v.w)
                     : "memory");
    }
}

__device__ __forceinline__ void scatter2_phase(
    const int* __restrict__ ei, const float* __restrict__ y,
    float* __restrict__ h, int e, int gtid, int T) {
#pragma unroll 4
    for (int t = gtid; t < e; t += T) {
        int src = __ldg(ei + t);
        int dst = __ldg(ei + e + t);
        float2 v = __ldg(reinterpret_cast<const float2*>(y + 2 * (size_t)src));
        float* p = h + 2 * (size_t)dst;
        asm volatile("red.global.add.v2.f32 [%0], {%1, %2};"
                     :: "l"(p), "f"(v.x), "f"(v.y)
                     : "memory");
    }
}

// ---------------------------------------------------------------------------
// One persistent kernel: all 7 stages, separated by grid barriers.
// ---------------------------------------------------------------------------
__global__ void __launch_bounds__(512)
gnn_persistent(const float* __restrict__ z, const int* __restrict__ ei,
               const float* __restrict__ Wrel1, const float* __restrict__ Wroot1, const float* __restrict__ b1,
               const float* __restrict__ Wrel2, const float* __restrict__ Wroot2, const float* __restrict__ b2,
               const float* __restrict__ Wrel3, const float* __restrict__ Wroot3, const float* __restrict__ b3,
               float* __restrict__ out, int n, int e) {
    __shared__ float s_w[2 * 64 * F1 + F1];   // max across phases (layer 1) + bias
    const int T = gridDim.x * blockDim.x;
    const int gtid = blockIdx.x * blockDim.x + threadIdx.x;

    // Layer 1
    transform_phase<64, F1, false>(z, Wrel1, Wroot1, b1, g_y1, g_h1, n, s_w, gtid, T);
    grid_sync();
    scatter_phase<F1>(ei, g_y1, g_h1, e, gtid, T);
    grid_sync();
    // Layer 2 (ReLU on read)
    transform_phase<F1, F2, true>(g_h1, Wrel2, Wroot2, b2, g_y2, g_h2, n, s_w, gtid, T);
    grid_sync();
    scatter_phase<F2>(ei, g_y2, g_h2, e, gtid, T);
    grid_sync();
    // Layer 3
    transform_phase<F2, F3, true>(g_h2, Wrel3, Wroot3, b3, g_y3, g_h3, n, s_w, gtid, T);
    grid_sync();
    scatter2_phase(ei, g_y3, g_h3, e, gtid, T);
    grid_sync();
    // Softmax (2-class) -> out
    for (int i = gtid; i < n; i += T) {
        float2 v = *reinterpret_cast<const float2*>(g_h3 + 2 * (size_t)i);
        float m  = fmaxf(v.x, v.y);
        float ea = __expf(v.x - m);
        float eb = __expf(v.y - m);
        float inv = 1.0f / (ea + eb);
        reinterpret_cast<float2*>(out)[i] = make_float2(ea * inv, eb * inv);
    }
}

extern "C" void kernel_launch(void* const* d_in, const int* in_sizes, int n_in,
                              void* d_out, int out_size) {
    const float* z      = (const float*)d_in[0];
    const int*   ei     = (const int*)d_in[1];   // int32 (JAX x64 disabled)
    const float* Wrel1  = (const float*)d_in[2];
    const float* Wroot1 = (const float*)d_in[3];
    const float* b1     = (const float*)d_in[4];
    const float* Wrel2  = (const float*)d_in[5];
    const float* Wroot2 = (const float*)d_in[6];
    const float* b2     = (const float*)d_in[7];
    const float* Wrel3  = (const float*)d_in[8];
    const float* Wroot3 = (const float*)d_in[9];
    const float* b3     = (const float*)d_in[10];

    const int n = in_sizes[0] / 64;   // 100000
    const int e = in_sizes[1] / 2;    // 1600000

    // Persistent sizing: all blocks must be simultaneously resident.
    int dev = 0, sm = 0, occ = 0;
    cudaGetDevice(&dev);
    cudaDeviceGetAttribute(&sm, cudaDevAttrMultiProcessorCount, dev);
    cudaOccupancyMaxActiveBlocksPerMultiprocessor(&occ, gnn_persistent, 512, 0);
    if (occ < 1) occ = 1;
    int blocks = sm * occ;

    gnn_persistent<<<blocks, 512>>>(z, ei,
                                    Wrel1, Wroot1, b1,
                                    Wrel2, Wroot2, b2,
                                    Wrel3, Wroot3, b3,
                                    (float*)d_out, n, e);
}